// round 6
// baseline (speedup 1.0000x reference)
#include <cuda_runtime.h>
#include <cstdint>
#include <math.h>

#define NHID   1024
#define LSTEPS 1024
#define TPB    128          // 4 warps per CTA, one CTA per batch row
#define NPT    8            // neurons per thread (contiguous)
#define NPAIR  4            // f32x2 pairs per thread
#define BMAX   4096

typedef unsigned long long u64;

__device__ int g_spiked[BMAX];   // per-row "any RF spike ever" flag

// ---- packed f32x2 ops (sm_100+) ----
__device__ __forceinline__ float2 ffma2(float2 a, float2 b, float2 c) {
    float2 d;
    asm("fma.rn.f32x2 %0, %1, %2, %3;"
        : "=l"(*(u64*)&d) : "l"(*(u64*)&a), "l"(*(u64*)&b), "l"(*(u64*)&c));
    return d;
}
__device__ __forceinline__ float2 fadd2(float2 a, float2 b) {
    float2 d;
    asm("add.rn.f32x2 %0, %1, %2;"
        : "=l"(*(u64*)&d) : "l"(*(u64*)&a), "l"(*(u64*)&b));
    return d;
}
__device__ __forceinline__ float2 fmul2(float2 a, float2 b) {
    float2 d;
    asm("mul.rn.f32x2 %0, %1, %2;"
        : "=l"(*(u64*)&d) : "l"(*(u64*)&a), "l"(*(u64*)&b));
    return d;
}

// Barrier + OR-reduction across the CTA in one BAR.RED instruction.
__device__ __forceinline__ bool bar_red_or(bool p) {
    unsigned r;
    asm volatile(
        "{\n\t"
        ".reg .pred pi, po;\n\t"
        "setp.ne.u32 pi, %1, 0;\n\t"
        "bar.red.or.pred po, 0, pi;\n\t"
        "selp.u32 %0, 1, 0, po;\n\t"
        "}"
        : "=r"(r) : "r"((unsigned)p) : "memory");
    return r != 0;
}

// ======================= COLD KERNEL (barrier-free mainloop) ==============
// While no RF spike has EVER occurred in a row, ref/ft/fts are exactly 0 and
// there is no recurrent coupling; alpha=beta=0 means an RF spike would not
// alter hy/hz. So the uncoupled lif/hy/hz trajectory is valid up to and
// including the first crossing, and "did any neuron ever cross hy>1" decides
// everything (ref==0 => spike cond (hy-1-ref)>0 <=> hy>1, exact by Sterbenz).
// Writes zeros + the per-row flag; a second kernel redoes flagged rows.
// hz is kept rescaled as hzs = dt*hz: hy += hzs; hzs = hzs*(1-dt*eps)
// + (-dt^2*gamma)*hy + spike*dt^2*sg.  (Saves the DT2 constant pair.)
__global__ __launch_bounds__(TPB, 7)
void coesn_cold(const float* __restrict__ x,      // (B, L)
                const float* __restrict__ x2h,    // (NHID)
                const float* __restrict__ bias,   // (NHID)
                const float* __restrict__ gamma_, // (NHID)
                const float* __restrict__ eps_,   // (NHID)
                const float* __restrict__ sgain,  // scalar
                float* __restrict__ out)          // (B, 2*NHID)
{
    __shared__ float xs[LSTEPS];

    const int tid = threadIdx.x;
    const int b   = blockIdx.x;

    {
        const float4* xr = (const float4*)(x + (size_t)b * LSTEPS);
        ((float4*)xs)[tid]       = xr[tid];
        ((float4*)xs)[tid + TPB] = xr[tid + TPB];
    }

    const float dt = 0.01f;
    const float A  = 1.0f - dt / 20.0f;             // LIF decay
    const float sg = *sgain;

    const float2 A2   = make_float2(A, A);
    const float2 NDS2 = make_float2(-dt * dt * sg, -dt * dt * sg);

    float2 W2[NPAIR], B2[NPAIR], EZ2[NPAIR], GN2[NPAIR];
    #pragma unroll
    for (int i = 0; i < 2; ++i) {
        float4 a;
        a = ((const float4*)x2h)[tid * 2 + i];
        W2[2*i]   = make_float2(dt*a.x, dt*a.y);
        W2[2*i+1] = make_float2(dt*a.z, dt*a.w);
        a = ((const float4*)bias)[tid * 2 + i];
        B2[2*i]   = make_float2(dt*a.x, dt*a.y);
        B2[2*i+1] = make_float2(dt*a.z, dt*a.w);
        a = ((const float4*)eps_)[tid * 2 + i];
        EZ2[2*i]   = make_float2(1.f-dt*a.x, 1.f-dt*a.y);
        EZ2[2*i+1] = make_float2(1.f-dt*a.z, 1.f-dt*a.w);
        a = ((const float4*)gamma_)[tid * 2 + i];
        GN2[2*i]   = make_float2(-dt*dt*a.x, -dt*dt*a.y);
        GN2[2*i+1] = make_float2(-dt*dt*a.z, -dt*dt*a.w);
    }

    float2 lif2[NPAIR], hy2[NPAIR], hzs2[NPAIR];
    #pragma unroll
    for (int p = 0; p < NPAIR; ++p) {
        lif2[p] = make_float2(0.f, 0.f);
        hy2[p]  = make_float2(0.f, 0.f);
        hzs2[p] = make_float2(0.f, 0.f);
    }
    float2 mx2 = make_float2(-1.f, -1.f);   // running max of hy (packed lanes)

    __syncthreads();   // xs ready

    #pragma unroll 1
    for (int tq = 0; tq < LSTEPS / 4; ++tq) {
        const float4 xq = ((const float4*)xs)[tq];
        const float xtv[4] = {xq.x, xq.y, xq.z, xq.w};
        #pragma unroll
        for (int s = 0; s < 4; ++s) {
            const float2 XT2 = make_float2(xtv[s], xtv[s]);
            #pragma unroll
            for (int p = 0; p < NPAIR; ++p) {
                float2 I = ffma2(XT2, W2[p], B2[p]);        // dt*(xt*w + b)
                lif2[p] = ffma2(lif2[p], A2, I);            // v = v*A + dt*I
                const bool l0 = lif2[p].x > 1.0f;
                const bool l1 = lif2[p].y > 1.0f;
                float2 ms = make_float2(l0 ? -1.0f : 0.0f, l1 ? -1.0f : 0.0f);
                lif2[p] = fadd2(lif2[p], ms);               // soft reset
                float2 k = fmul2(ms, NDS2);                 // +dt^2*sg on spike
                hzs2[p] = ffma2(hzs2[p], EZ2[p], ffma2(GN2[p], hy2[p], k));
                hy2[p]  = fadd2(hy2[p], hzs2[p]);           // hy += dt*hz
                mx2.x = fmaxf(mx2.x, hy2[p].x);
                mx2.y = fmaxf(mx2.y, hy2[p].y);
            }
        }
    }

    const bool ever = bar_red_or(fmaxf(mx2.x, mx2.y) > 1.0f);
    if (tid == 0) g_spiked[b] = ever ? 1 : 0;

    // Zero output (correct if no spike; fix kernel overwrites otherwise).
    float* o0 = out + (size_t)b * (2 * NHID) + tid * NPT;
    float* o1 = o0 + NHID;
    const float4 z = make_float4(0.f, 0.f, 0.f, 0.f);
    ((float4*)o0)[0] = z; ((float4*)o0)[1] = z;
    ((float4*)o1)[0] = z; ((float4*)o1)[1] = z;
}

// ======================= FIX KERNEL (general coupled path) ================
// Runs the full dynamics with recurrent h2h gather + ref/ft/fts, only for
// rows whose flag is set (expected: none).
__global__ __launch_bounds__(TPB)
void coesn_fix(const float* __restrict__ x,
               const float* __restrict__ x2h,
               const float* __restrict__ h2h,
               const float* __restrict__ bias,
               const float* __restrict__ gamma_,
               const float* __restrict__ eps_,
               const float* __restrict__ sgain,
               float* __restrict__ out)
{
    const int b = blockIdx.x;
    if (g_spiked[b] == 0) return;      // uniform per CTA

    __shared__ float    xs[LSTEPS];
    __shared__ unsigned smask[TPB];
    __shared__ float    sref[NHID], sft[NHID], sfts[NHID];

    const int tid = threadIdx.x;

    {
        const float4* xr = (const float4*)(x + (size_t)b * LSTEPS);
        ((float4*)xs)[tid]       = xr[tid];
        ((float4*)xs)[tid + TPB] = xr[tid + TPB];
    }

    const float dt = 0.01f;
    const float A  = 1.0f - dt / 20.0f;
    const float sg = *sgain;
    const float RD = expf(-dt / 0.25f);
    const float FD = expf(-dt / 10.0f);

    const float2 A2     = make_float2(A, A);
    const float2 DT2    = make_float2(dt, dt);
    const float2 NDTSG2 = make_float2(-dt * sg, -dt * sg);
    const float2 RD2    = make_float2(RD, RD);
    const float2 FD2    = make_float2(FD, FD);

    float2 W2[NPAIR], B2[NPAIR], EZ2[NPAIR], GN2[NPAIR];
    #pragma unroll
    for (int i = 0; i < 2; ++i) {
        float4 a;
        a = ((const float4*)x2h)[tid * 2 + i];
        W2[2*i]   = make_float2(dt*a.x, dt*a.y);
        W2[2*i+1] = make_float2(dt*a.z, dt*a.w);
        a = ((const float4*)bias)[tid * 2 + i];
        B2[2*i]   = make_float2(dt*a.x, dt*a.y);
        B2[2*i+1] = make_float2(dt*a.z, dt*a.w);
        a = ((const float4*)eps_)[tid * 2 + i];
        EZ2[2*i]   = make_float2(1.f-dt*a.x, 1.f-dt*a.y);
        EZ2[2*i+1] = make_float2(1.f-dt*a.z, 1.f-dt*a.w);
        a = ((const float4*)gamma_)[tid * 2 + i];
        GN2[2*i]   = make_float2(-dt*a.x, -dt*a.y);
        GN2[2*i+1] = make_float2(-dt*a.z, -dt*a.w);
    }

    float2 lif2[NPAIR], hy2[NPAIR], hz2[NPAIR];
    #pragma unroll
    for (int p = 0; p < NPAIR; ++p) {
        lif2[p] = make_float2(0.f, 0.f);
        hy2[p]  = make_float2(0.f, 0.f);
        hz2[p]  = make_float2(0.f, 0.f);
    }
    #pragma unroll
    for (int q = 0; q < NPT; ++q) {
        const int n = tid * NPT + q;
        sref[n] = 0.f; sft[n] = 0.f; sfts[n] = 0.f;
    }
    smask[tid] = 0u;
    __syncthreads();

    bool prev = false;
    #pragma unroll 1
    for (int t = 0; t < LSTEPS; ++t) {
        const float  xt  = xs[t];
        const float2 XT2 = make_float2(xt, xt);

        float2 acc[NPAIR];
        #pragma unroll
        for (int p = 0; p < NPAIR; ++p) acc[p] = make_float2(0.f, 0.f);

        if (prev) {
            for (int w = 0; w < TPB; ++w) {
                unsigned mm_ = smask[w];
                while (mm_) {
                    const int k = __ffs(mm_) - 1; mm_ &= mm_ - 1;
                    const int j = w * NPT + k;
                    const float4* hp =
                        (const float4*)(h2h + (size_t)j * NHID + tid * NPT);
                    #pragma unroll
                    for (int i = 0; i < 2; ++i) {
                        float4 h = __ldg(hp + i);
                        acc[2*i].x   += h.x; acc[2*i].y   += h.y;
                        acc[2*i+1].x += h.z; acc[2*i+1].y += h.w;
                    }
                }
            }
        }

        bool any = false;
        unsigned msk = 0;
        #pragma unroll
        for (int p = 0; p < NPAIR; ++p) {
            float2 I = ffma2(XT2, W2[p], B2[p]);
            I = ffma2(DT2, acc[p], I);
            lif2[p] = ffma2(lif2[p], A2, I);
            const bool l0 = lif2[p].x > 1.0f;
            const bool l1 = lif2[p].y > 1.0f;
            float2 ms = make_float2(l0 ? -1.0f : 0.0f, l1 ? -1.0f : 0.0f);
            lif2[p] = fadd2(lif2[p], ms);
            float2 k = fmul2(ms, NDTSG2);
            hz2[p] = ffma2(hz2[p], EZ2[p], ffma2(GN2[p], hy2[p], k));
            hy2[p] = ffma2(DT2, hz2[p], hy2[p]);

            const int n = tid * NPT + 2 * p;
            float2 rf = make_float2(sref[n], sref[n+1]);
            const bool q0 = (hy2[p].x - 1.0f) > rf.x;
            const bool q1 = (hy2[p].y - 1.0f) > rf.y;
            float2 sn = make_float2(q0 ? 1.0f : 0.0f, q1 ? 1.0f : 0.0f);
            rf = ffma2(rf, RD2, sn);
            sref[n] = rf.x; sref[n+1] = rf.y;
            float2 f = make_float2(sft[n], sft[n+1]);
            f = ffma2(f, FD2, sn);
            sft[n] = f.x; sft[n+1] = f.y;
            sfts[n]   += f.x;
            sfts[n+1] += f.y;
            any = any || q0 || q1;
            msk |= (q0 ? 1u : 0u) << (2 * p);
            msk |= (q1 ? 1u : 0u) << (2 * p + 1);
        }
        smask[tid] = msk;
        prev = bar_red_or(any);
    }

    const float invL = 1.0f / (float)LSTEPS;
    float* o0 = out + (size_t)b * (2 * NHID) + tid * NPT;
    float* o1 = o0 + NHID;
    #pragma unroll
    for (int i = 0; i < 2; ++i) {
        const int n = tid * NPT + 4 * i;
        ((float4*)o0)[i] = make_float4(sfts[n]*invL, sfts[n+1]*invL,
                                       sfts[n+2]*invL, sfts[n+3]*invL);
        ((float4*)o1)[i] = make_float4(sft[n], sft[n+1], sft[n+2], sft[n+3]);
    }
}

extern "C" void kernel_launch(void* const* d_in, const int* in_sizes, int n_in,
                              void* d_out, int out_size)
{
    const float* x    = (const float*)d_in[0];
    const float* x2h  = (const float*)d_in[1];
    const float* h2h  = (const float*)d_in[2];
    const float* bias = (const float*)d_in[3];
    const float* gam  = (const float*)d_in[4];
    const float* eps  = (const float*)d_in[5];
    const float* sg   = (const float*)d_in[6];

    const int B = in_sizes[0] / LSTEPS;   // N_INP == 1
    coesn_cold<<<B, TPB>>>(x, x2h, bias, gam, eps, sg, (float*)d_out);
    coesn_fix <<<B, TPB>>>(x, x2h, h2h, bias, gam, eps, sg, (float*)d_out);
}

// round 7
// speedup vs baseline: 1.0129x; 1.0129x over previous
#include <cuda_runtime.h>
#include <cstdint>
#include <math.h>

#define NHID   1024
#define LSTEPS 1024
#define TPB    128          // 4 warps per CTA, one CTA per batch row
#define NPT    8            // neurons per thread (contiguous)
#define NPAIR  4            // f32x2 pairs per thread
#define BMAX   4096

typedef unsigned long long u64;

__device__ int g_spiked[BMAX];   // per-row "any RF spike ever" flag

// ---- packed f32x2 ops (sm_100+) ----
__device__ __forceinline__ float2 ffma2(float2 a, float2 b, float2 c) {
    float2 d;
    asm("fma.rn.f32x2 %0, %1, %2, %3;"
        : "=l"(*(u64*)&d) : "l"(*(u64*)&a), "l"(*(u64*)&b), "l"(*(u64*)&c));
    return d;
}
__device__ __forceinline__ float2 fadd2(float2 a, float2 b) {
    float2 d;
    asm("add.rn.f32x2 %0, %1, %2;"
        : "=l"(*(u64*)&d) : "l"(*(u64*)&a), "l"(*(u64*)&b));
    return d;
}
__device__ __forceinline__ float2 fmul2(float2 a, float2 b) {
    float2 d;
    asm("mul.rn.f32x2 %0, %1, %2;"
        : "=l"(*(u64*)&d) : "l"(*(u64*)&a), "l"(*(u64*)&b));
    return d;
}

// Barrier + OR-reduction across the CTA in one BAR.RED instruction.
__device__ __forceinline__ bool bar_red_or(bool p) {
    unsigned r;
    asm volatile(
        "{\n\t"
        ".reg .pred pi, po;\n\t"
        "setp.ne.u32 pi, %1, 0;\n\t"
        "bar.red.or.pred po, 0, pi;\n\t"
        "selp.u32 %0, 1, 0, po;\n\t"
        "}"
        : "=r"(r) : "r"((unsigned)p) : "memory");
    return r != 0;
}

// ======================= COLD KERNEL (barrier-free mainloop) ==============
// While no RF spike has EVER occurred in a row, ref/ft/fts are exactly 0 and
// there is no recurrent coupling; alpha=beta=0 means an RF spike would not
// alter hy/hz. So the uncoupled lif/hy/hz trajectory is valid up to and
// including the first crossing; "did any neuron ever cross hy>1" (ref==0 =>
// spike cond (hy-1-ref)>0 <=> hy>1, exact by Sterbenz) decides everything.
// hz kept rescaled as hzs = dt*hz:
//   hzs = hzs*(1-dt*eps) + (-dt^2*gamma)*hy + spike*(dt^2*sg);  hy += hzs.
// Pipe-balanced inner body (RF-banking aware):
//   fma : ffma2(I) rt3 | fmaf-imm x2 rt1 | fadd2(reset) rt2 |
//         ffma2(inner) rt3 | ffma2(outer) rt3 | fadd2(hy) rt2   = 15 cyc
//   alu : FSETP x2 | SEL(ms) x2 | SEL(k) x2 | FMNMX x2          = 16 cyc
__global__ __launch_bounds__(TPB, 6)
void coesn_cold(const float* __restrict__ x,      // (B, L)
                const float* __restrict__ x2h,    // (NHID)
                const float* __restrict__ bias,   // (NHID)
                const float* __restrict__ gamma_, // (NHID)
                const float* __restrict__ eps_,   // (NHID)
                const float* __restrict__ sgain,  // scalar
                float* __restrict__ out)          // (B, 2*NHID)
{
    __shared__ float xs2[2 * LSTEPS];   // duplicated: xs2[2t]=xs2[2t+1]=x[t]

    const int tid = threadIdx.x;
    const int b   = blockIdx.x;

    // Stage duplicated input: each thread handles 8 source floats.
    {
        const float4* xr = (const float4*)(x + (size_t)b * LSTEPS);
        #pragma unroll
        for (int i = 0; i < 2; ++i) {
            float4 v = xr[tid + i * TPB];
            float4* dst = ((float4*)xs2) + 2 * (tid + i * TPB);
            dst[0] = make_float4(v.x, v.x, v.y, v.y);
            dst[1] = make_float4(v.z, v.z, v.w, v.w);
        }
    }

    const float dt = 0.01f;
    const float A  = 1.0f - dt / 20.0f;             // LIF decay (imm)
    const float kick = dt * dt * (*sgain);          // hzs kick per LIF spike

    float2 W2[NPAIR], B2[NPAIR], EZ2[NPAIR], GN2[NPAIR];
    #pragma unroll
    for (int i = 0; i < 2; ++i) {
        float4 a;
        a = ((const float4*)x2h)[tid * 2 + i];
        W2[2*i]   = make_float2(dt*a.x, dt*a.y);
        W2[2*i+1] = make_float2(dt*a.z, dt*a.w);
        a = ((const float4*)bias)[tid * 2 + i];
        B2[2*i]   = make_float2(dt*a.x, dt*a.y);
        B2[2*i+1] = make_float2(dt*a.z, dt*a.w);
        a = ((const float4*)eps_)[tid * 2 + i];
        EZ2[2*i]   = make_float2(1.f-dt*a.x, 1.f-dt*a.y);
        EZ2[2*i+1] = make_float2(1.f-dt*a.z, 1.f-dt*a.w);
        a = ((const float4*)gamma_)[tid * 2 + i];
        GN2[2*i]   = make_float2(-dt*dt*a.x, -dt*dt*a.y);
        GN2[2*i+1] = make_float2(-dt*dt*a.z, -dt*dt*a.w);
    }

    float2 lif2[NPAIR], hy2[NPAIR], hzs2[NPAIR];
    #pragma unroll
    for (int p = 0; p < NPAIR; ++p) {
        lif2[p] = make_float2(0.f, 0.f);
        hy2[p]  = make_float2(0.f, 0.f);
        hzs2[p] = make_float2(0.f, 0.f);
    }
    float2 mx2 = make_float2(-1.f, -1.f);   // running max of hy (both lanes)

    __syncthreads();   // xs2 ready

    #pragma unroll 1
    for (int t4 = 0; t4 < LSTEPS / 4; ++t4) {
        #pragma unroll
        for (int s = 0; s < 4; ++s) {
            const float2 XT2 = ((const float2*)xs2)[t4 * 4 + s];  // LDS.64
            #pragma unroll
            for (int p = 0; p < NPAIR; ++p) {
                float2 I = ffma2(XT2, W2[p], B2[p]);     // dt*(xt*w + b)  rt3
                lif2[p].x = fmaf(lif2[p].x, A, I.x);     // FFMA-imm       rt1
                lif2[p].y = fmaf(lif2[p].y, A, I.y);     // FFMA-imm       rt1
                const bool l0 = lif2[p].x > 1.0f;
                const bool l1 = lif2[p].y > 1.0f;
                float2 ms, k;
                ms.x = l0 ? -1.0f : 0.0f;                // SEL
                ms.y = l1 ? -1.0f : 0.0f;                // SEL
                k.x  = l0 ? kick : 0.0f;                 // SEL
                k.y  = l1 ? kick : 0.0f;                 // SEL
                lif2[p] = fadd2(lif2[p], ms);            // soft reset     rt2
                hzs2[p] = ffma2(hzs2[p], EZ2[p],
                                ffma2(GN2[p], hy2[p], k));   // rt3 + rt3
                hy2[p]  = fadd2(hy2[p], hzs2[p]);        // hy += dt*hz    rt2
                mx2.x = fmaxf(mx2.x, hy2[p].x);          // FMNMX (alu)
                mx2.y = fmaxf(mx2.y, hy2[p].y);          // FMNMX (alu)
            }
        }
    }

    const bool ever = bar_red_or(fmaxf(mx2.x, mx2.y) > 1.0f);
    if (tid == 0) g_spiked[b] = ever ? 1 : 0;

    // Zero output (correct if no spike; fix kernel overwrites otherwise).
    float* o0 = out + (size_t)b * (2 * NHID) + tid * NPT;
    float* o1 = o0 + NHID;
    const float4 z = make_float4(0.f, 0.f, 0.f, 0.f);
    ((float4*)o0)[0] = z; ((float4*)o0)[1] = z;
    ((float4*)o1)[0] = z; ((float4*)o1)[1] = z;
}

// ======================= FIX KERNEL (general coupled path) ================
// Full dynamics with recurrent h2h gather + ref/ft/fts, only for flagged rows
// (expected: none on this data; correctness safety net for any input).
__global__ __launch_bounds__(TPB)
void coesn_fix(const float* __restrict__ x,
               const float* __restrict__ x2h,
               const float* __restrict__ h2h,
               const float* __restrict__ bias,
               const float* __restrict__ gamma_,
               const float* __restrict__ eps_,
               const float* __restrict__ sgain,
               float* __restrict__ out)
{
    const int b = blockIdx.x;
    if (g_spiked[b] == 0) return;      // uniform per CTA

    __shared__ float    xs[LSTEPS];
    __shared__ unsigned smask[TPB];
    __shared__ float    sref[NHID], sft[NHID], sfts[NHID];

    const int tid = threadIdx.x;

    {
        const float4* xr = (const float4*)(x + (size_t)b * LSTEPS);
        ((float4*)xs)[tid]       = xr[tid];
        ((float4*)xs)[tid + TPB] = xr[tid + TPB];
    }

    const float dt = 0.01f;
    const float A  = 1.0f - dt / 20.0f;
    const float sg = *sgain;
    const float RD = expf(-dt / 0.25f);
    const float FD = expf(-dt / 10.0f);

    const float2 A2     = make_float2(A, A);
    const float2 DT2    = make_float2(dt, dt);
    const float2 NDTSG2 = make_float2(-dt * sg, -dt * sg);
    const float2 RD2    = make_float2(RD, RD);
    const float2 FD2    = make_float2(FD, FD);

    float2 W2[NPAIR], B2[NPAIR], EZ2[NPAIR], GN2[NPAIR];
    #pragma unroll
    for (int i = 0; i < 2; ++i) {
        float4 a;
        a = ((const float4*)x2h)[tid * 2 + i];
        W2[2*i]   = make_float2(dt*a.x, dt*a.y);
        W2[2*i+1] = make_float2(dt*a.z, dt*a.w);
        a = ((const float4*)bias)[tid * 2 + i];
        B2[2*i]   = make_float2(dt*a.x, dt*a.y);
        B2[2*i+1] = make_float2(dt*a.z, dt*a.w);
        a = ((const float4*)eps_)[tid * 2 + i];
        EZ2[2*i]   = make_float2(1.f-dt*a.x, 1.f-dt*a.y);
        EZ2[2*i+1] = make_float2(1.f-dt*a.z, 1.f-dt*a.w);
        a = ((const float4*)gamma_)[tid * 2 + i];
        GN2[2*i]   = make_float2(-dt*a.x, -dt*a.y);
        GN2[2*i+1] = make_float2(-dt*a.z, -dt*a.w);
    }

    float2 lif2[NPAIR], hy2[NPAIR], hz2[NPAIR];
    #pragma unroll
    for (int p = 0; p < NPAIR; ++p) {
        lif2[p] = make_float2(0.f, 0.f);
        hy2[p]  = make_float2(0.f, 0.f);
        hz2[p]  = make_float2(0.f, 0.f);
    }
    #pragma unroll
    for (int q = 0; q < NPT; ++q) {
        const int n = tid * NPT + q;
        sref[n] = 0.f; sft[n] = 0.f; sfts[n] = 0.f;
    }
    smask[tid] = 0u;
    __syncthreads();

    bool prev = false;
    #pragma unroll 1
    for (int t = 0; t < LSTEPS; ++t) {
        const float  xt  = xs[t];
        const float2 XT2 = make_float2(xt, xt);

        float2 acc[NPAIR];
        #pragma unroll
        for (int p = 0; p < NPAIR; ++p) acc[p] = make_float2(0.f, 0.f);

        if (prev) {
            for (int w = 0; w < TPB; ++w) {
                unsigned mm_ = smask[w];
                while (mm_) {
                    const int k = __ffs(mm_) - 1; mm_ &= mm_ - 1;
                    const int j = w * NPT + k;
                    const float4* hp =
                        (const float4*)(h2h + (size_t)j * NHID + tid * NPT);
                    #pragma unroll
                    for (int i = 0; i < 2; ++i) {
                        float4 h = __ldg(hp + i);
                        acc[2*i].x   += h.x; acc[2*i].y   += h.y;
                        acc[2*i+1].x += h.z; acc[2*i+1].y += h.w;
                    }
                }
            }
        }

        bool any = false;
        unsigned msk = 0;
        #pragma unroll
        for (int p = 0; p < NPAIR; ++p) {
            float2 I = ffma2(XT2, W2[p], B2[p]);
            I = ffma2(DT2, acc[p], I);
            lif2[p] = ffma2(lif2[p], A2, I);
            const bool l0 = lif2[p].x > 1.0f;
            const bool l1 = lif2[p].y > 1.0f;
            float2 ms = make_float2(l0 ? -1.0f : 0.0f, l1 ? -1.0f : 0.0f);
            lif2[p] = fadd2(lif2[p], ms);
            float2 k = fmul2(ms, NDTSG2);
            hz2[p] = ffma2(hz2[p], EZ2[p], ffma2(GN2[p], hy2[p], k));
            hy2[p] = ffma2(DT2, hz2[p], hy2[p]);

            const int n = tid * NPT + 2 * p;
            float2 rf = make_float2(sref[n], sref[n+1]);
            const bool q0 = (hy2[p].x - 1.0f) > rf.x;
            const bool q1 = (hy2[p].y - 1.0f) > rf.y;
            float2 sn = make_float2(q0 ? 1.0f : 0.0f, q1 ? 1.0f : 0.0f);
            rf = ffma2(rf, RD2, sn);
            sref[n] = rf.x; sref[n+1] = rf.y;
            float2 f = make_float2(sft[n], sft[n+1]);
            f = ffma2(f, FD2, sn);
            sft[n] = f.x; sft[n+1] = f.y;
            sfts[n]   += f.x;
            sfts[n+1] += f.y;
            any = any || q0 || q1;
            msk |= (q0 ? 1u : 0u) << (2 * p);
            msk |= (q1 ? 1u : 0u) << (2 * p + 1);
        }
        smask[tid] = msk;
        prev = bar_red_or(any);
    }

    const float invL = 1.0f / (float)LSTEPS;
    float* o0 = out + (size_t)b * (2 * NHID) + tid * NPT;
    float* o1 = o0 + NHID;
    #pragma unroll
    for (int i = 0; i < 2; ++i) {
        const int n = tid * NPT + 4 * i;
        ((float4*)o0)[i] = make_float4(sfts[n]*invL, sfts[n+1]*invL,
                                       sfts[n+2]*invL, sfts[n+3]*invL);
        ((float4*)o1)[i] = make_float4(sft[n], sft[n+1], sft[n+2], sft[n+3]);
    }
}

extern "C" void kernel_launch(void* const* d_in, const int* in_sizes, int n_in,
                              void* d_out, int out_size)
{
    const float* x    = (const float*)d_in[0];
    const float* x2h  = (const float*)d_in[1];
    const float* h2h  = (const float*)d_in[2];
    const float* bias = (const float*)d_in[3];
    const float* gam  = (const float*)d_in[4];
    const float* eps  = (const float*)d_in[5];
    const float* sg   = (const float*)d_in[6];

    const int B = in_sizes[0] / LSTEPS;   // N_INP == 1
    coesn_cold<<<B, TPB>>>(x, x2h, bias, gam, eps, sg, (float*)d_out);
    coesn_fix <<<B, TPB>>>(x, x2h, h2h, bias, gam, eps, sg, (float*)d_out);
}

// round 8
// speedup vs baseline: 1.0317x; 1.0185x over previous
#include <cuda_runtime.h>
#include <cstdint>
#include <math.h>

#define NHID   1024
#define LSTEPS 1024
#define TPBC   256          // cold kernel: 8 warps per CTA, one CTA per row
#define NPTC   4            // cold: neurons per thread
#define NPRC   2            // cold: f32x2 pairs per thread
#define TPBF   128          // fix kernel
#define NPTF   8
#define NPRF   4
#define BMAX   4096

typedef unsigned long long u64;

__device__ int g_spiked[BMAX];   // per-row "any RF spike ever" flag

// ---- packed f32x2 ops (sm_100+) ----
__device__ __forceinline__ float2 ffma2(float2 a, float2 b, float2 c) {
    float2 d;
    asm("fma.rn.f32x2 %0, %1, %2, %3;"
        : "=l"(*(u64*)&d) : "l"(*(u64*)&a), "l"(*(u64*)&b), "l"(*(u64*)&c));
    return d;
}
__device__ __forceinline__ float2 fadd2(float2 a, float2 b) {
    float2 d;
    asm("add.rn.f32x2 %0, %1, %2;"
        : "=l"(*(u64*)&d) : "l"(*(u64*)&a), "l"(*(u64*)&b));
    return d;
}
__device__ __forceinline__ float2 fmul2(float2 a, float2 b) {
    float2 d;
    asm("mul.rn.f32x2 %0, %1, %2;"
        : "=l"(*(u64*)&d) : "l"(*(u64*)&a), "l"(*(u64*)&b));
    return d;
}

// Barrier + OR-reduction across the CTA in one BAR.RED instruction.
__device__ __forceinline__ bool bar_red_or(bool p) {
    unsigned r;
    asm volatile(
        "{\n\t"
        ".reg .pred pi, po;\n\t"
        "setp.ne.u32 pi, %1, 0;\n\t"
        "bar.red.or.pred po, 0, pi;\n\t"
        "selp.u32 %0, 1, 0, po;\n\t"
        "}"
        : "=r"(r) : "r"((unsigned)p) : "memory");
    return r != 0;
}

// ======================= COLD KERNEL (barrier-free mainloop) ==============
// While no RF spike has EVER occurred in a row, ref/ft/fts are exactly 0 and
// there is no recurrent coupling; alpha=beta=0 means an RF spike would not
// alter hy/hz. The uncoupled lif/hy/hzs trajectory is therefore valid up to
// and including the first crossing; "did any neuron ever cross hy>1" (ref==0
// => spike cond (hy-1-ref)>0 <=> hy>1, exact by Sterbenz) decides everything.
// hzs = dt*hz:  hzs' = hzs*(1-dt*eps) + (-dt^2*gamma)*hy + spike*(dt^2*sg);
//               hy  += hzs'.
// 14 issues per neuron-pair-step:
//   ffma2(I) ffma2(lif) FSETP x2 SEL x2 fadd2(reset) fmul2(kick)
//   ffma2 ffma2 fadd2(hy) FMNMX x2
__global__ __launch_bounds__(TPBC, 6)
void coesn_cold(const float* __restrict__ x,      // (B, L)
                const float* __restrict__ x2h,    // (NHID)
                const float* __restrict__ bias,   // (NHID)
                const float* __restrict__ gamma_, // (NHID)
                const float* __restrict__ eps_,   // (NHID)
                const float* __restrict__ sgain,  // scalar
                float* __restrict__ out)          // (B, 2*NHID)
{
    __shared__ float xs2[2 * LSTEPS];   // duplicated: xs2[2t]=xs2[2t+1]=x[t]

    const int tid = threadIdx.x;
    const int b   = blockIdx.x;

    // Stage duplicated input: each thread expands one float4 (4 steps).
    {
        const float4 v = ((const float4*)(x + (size_t)b * LSTEPS))[tid];
        float4* dst = ((float4*)xs2) + 2 * tid;
        dst[0] = make_float4(v.x, v.x, v.y, v.y);
        dst[1] = make_float4(v.z, v.z, v.w, v.w);
    }

    const float dt = 0.01f;
    const float A  = 1.0f - dt / 20.0f;             // LIF decay
    const float2 A2   = make_float2(A, A);
    const float2 NDS2 = make_float2(-dt * dt * (*sgain), -dt * dt * (*sgain));

    float2 W2[NPRC], B2[NPRC], EZ2[NPRC], GN2[NPRC];
    {
        float4 a;
        a = ((const float4*)x2h)[tid];
        W2[0] = make_float2(dt*a.x, dt*a.y);  W2[1] = make_float2(dt*a.z, dt*a.w);
        a = ((const float4*)bias)[tid];
        B2[0] = make_float2(dt*a.x, dt*a.y);  B2[1] = make_float2(dt*a.z, dt*a.w);
        a = ((const float4*)eps_)[tid];
        EZ2[0] = make_float2(1.f-dt*a.x, 1.f-dt*a.y);
        EZ2[1] = make_float2(1.f-dt*a.z, 1.f-dt*a.w);
        a = ((const float4*)gamma_)[tid];
        GN2[0] = make_float2(-dt*dt*a.x, -dt*dt*a.y);
        GN2[1] = make_float2(-dt*dt*a.z, -dt*dt*a.w);
    }

    float2 lif2[NPRC], hy2[NPRC], hzs2[NPRC];
    #pragma unroll
    for (int p = 0; p < NPRC; ++p) {
        lif2[p] = make_float2(0.f, 0.f);
        hy2[p]  = make_float2(0.f, 0.f);
        hzs2[p] = make_float2(0.f, 0.f);
    }
    float2 mx2 = make_float2(-1.f, -1.f);   // running max of hy (both lanes)

    __syncthreads();   // xs2 ready

    const float4* xv = (const float4*)xs2;
    #pragma unroll 1
    for (int it = 0; it < LSTEPS / 8; ++it) {
        float4 q[4];
        #pragma unroll
        for (int i = 0; i < 4; ++i) q[i] = xv[it * 4 + i];   // 8 steps of pairs
        #pragma unroll
        for (int s = 0; s < 8; ++s) {
            const float* qf = (const float*)q;
            const float2 XT2 = make_float2(qf[2 * s], qf[2 * s + 1]);
            #pragma unroll
            for (int p = 0; p < NPRC; ++p) {
                float2 I = ffma2(XT2, W2[p], B2[p]);       // dt*(xt*w + b)
                lif2[p] = ffma2(lif2[p], A2, I);           // v = v*A + dt*I
                const bool l0 = lif2[p].x > 1.0f;
                const bool l1 = lif2[p].y > 1.0f;
                float2 ms = make_float2(l0 ? -1.0f : 0.0f, l1 ? -1.0f : 0.0f);
                lif2[p] = fadd2(lif2[p], ms);              // soft reset
                float2 k = fmul2(ms, NDS2);                // +dt^2*sg on spike
                hzs2[p] = ffma2(hzs2[p], EZ2[p], ffma2(GN2[p], hy2[p], k));
                hy2[p]  = fadd2(hy2[p], hzs2[p]);          // hy += dt*hz
                mx2.x = fmaxf(mx2.x, hy2[p].x);
                mx2.y = fmaxf(mx2.y, hy2[p].y);
            }
        }
    }

    const bool ever = bar_red_or(fmaxf(mx2.x, mx2.y) > 1.0f);
    if (tid == 0) g_spiked[b] = ever ? 1 : 0;

    // Zero output (correct if no spike; fix kernel overwrites otherwise).
    float* o0 = out + (size_t)b * (2 * NHID) + tid * NPTC;
    const float4 z = make_float4(0.f, 0.f, 0.f, 0.f);
    ((float4*)o0)[0] = z;
    ((float4*)(o0 + NHID))[0] = z;
}

// ======================= FIX KERNEL (general coupled path) ================
// Full dynamics with recurrent h2h gather + ref/ft/fts, only for flagged rows
// (expected: none on this data; correctness safety net for any input).
__global__ __launch_bounds__(TPBF)
void coesn_fix(const float* __restrict__ x,
               const float* __restrict__ x2h,
               const float* __restrict__ h2h,
               const float* __restrict__ bias,
               const float* __restrict__ gamma_,
               const float* __restrict__ eps_,
               const float* __restrict__ sgain,
               float* __restrict__ out)
{
    const int b = blockIdx.x;
    if (g_spiked[b] == 0) return;      // uniform per CTA

    __shared__ float    xs[LSTEPS];
    __shared__ unsigned smask[TPBF];
    __shared__ float    sref[NHID], sft[NHID], sfts[NHID];

    const int tid = threadIdx.x;

    {
        const float4* xr = (const float4*)(x + (size_t)b * LSTEPS);
        ((float4*)xs)[tid]        = xr[tid];
        ((float4*)xs)[tid + TPBF] = xr[tid + TPBF];
    }

    const float dt = 0.01f;
    const float A  = 1.0f - dt / 20.0f;
    const float sg = *sgain;
    const float RD = expf(-dt / 0.25f);
    const float FD = expf(-dt / 10.0f);

    const float2 A2     = make_float2(A, A);
    const float2 DT2    = make_float2(dt, dt);
    const float2 NDTSG2 = make_float2(-dt * sg, -dt * sg);
    const float2 RD2    = make_float2(RD, RD);
    const float2 FD2    = make_float2(FD, FD);

    float2 W2[NPRF], B2[NPRF], EZ2[NPRF], GN2[NPRF];
    #pragma unroll
    for (int i = 0; i < 2; ++i) {
        float4 a;
        a = ((const float4*)x2h)[tid * 2 + i];
        W2[2*i]   = make_float2(dt*a.x, dt*a.y);
        W2[2*i+1] = make_float2(dt*a.z, dt*a.w);
        a = ((const float4*)bias)[tid * 2 + i];
        B2[2*i]   = make_float2(dt*a.x, dt*a.y);
        B2[2*i+1] = make_float2(dt*a.z, dt*a.w);
        a = ((const float4*)eps_)[tid * 2 + i];
        EZ2[2*i]   = make_float2(1.f-dt*a.x, 1.f-dt*a.y);
        EZ2[2*i+1] = make_float2(1.f-dt*a.z, 1.f-dt*a.w);
        a = ((const float4*)gamma_)[tid * 2 + i];
        GN2[2*i]   = make_float2(-dt*a.x, -dt*a.y);
        GN2[2*i+1] = make_float2(-dt*a.z, -dt*a.w);
    }

    float2 lif2[NPRF], hy2[NPRF], hz2[NPRF];
    #pragma unroll
    for (int p = 0; p < NPRF; ++p) {
        lif2[p] = make_float2(0.f, 0.f);
        hy2[p]  = make_float2(0.f, 0.f);
        hz2[p]  = make_float2(0.f, 0.f);
    }
    #pragma unroll
    for (int q = 0; q < NPTF; ++q) {
        const int n = tid * NPTF + q;
        sref[n] = 0.f; sft[n] = 0.f; sfts[n] = 0.f;
    }
    smask[tid] = 0u;
    __syncthreads();

    bool prev = false;
    #pragma unroll 1
    for (int t = 0; t < LSTEPS; ++t) {
        const float  xt  = xs[t];
        const float2 XT2 = make_float2(xt, xt);

        float2 acc[NPRF];
        #pragma unroll
        for (int p = 0; p < NPRF; ++p) acc[p] = make_float2(0.f, 0.f);

        if (prev) {
            for (int w = 0; w < TPBF; ++w) {
                unsigned mm_ = smask[w];
                while (mm_) {
                    const int k = __ffs(mm_) - 1; mm_ &= mm_ - 1;
                    const int j = w * NPTF + k;
                    const float4* hp =
                        (const float4*)(h2h + (size_t)j * NHID + tid * NPTF);
                    #pragma unroll
                    for (int i = 0; i < 2; ++i) {
                        float4 h = __ldg(hp + i);
                        acc[2*i].x   += h.x; acc[2*i].y   += h.y;
                        acc[2*i+1].x += h.z; acc[2*i+1].y += h.w;
                    }
                }
            }
        }

        bool any = false;
        unsigned msk = 0;
        #pragma unroll
        for (int p = 0; p < NPRF; ++p) {
            float2 I = ffma2(XT2, W2[p], B2[p]);
            I = ffma2(DT2, acc[p], I);
            lif2[p] = ffma2(lif2[p], A2, I);
            const bool l0 = lif2[p].x > 1.0f;
            const bool l1 = lif2[p].y > 1.0f;
            float2 ms = make_float2(l0 ? -1.0f : 0.0f, l1 ? -1.0f : 0.0f);
            lif2[p] = fadd2(lif2[p], ms);
            float2 k = fmul2(ms, NDTSG2);
            hz2[p] = ffma2(hz2[p], EZ2[p], ffma2(GN2[p], hy2[p], k));
            hy2[p] = ffma2(DT2, hz2[p], hy2[p]);

            const int n = tid * NPTF + 2 * p;
            float2 rf = make_float2(sref[n], sref[n+1]);
            const bool q0 = (hy2[p].x - 1.0f) > rf.x;
            const bool q1 = (hy2[p].y - 1.0f) > rf.y;
            float2 sn = make_float2(q0 ? 1.0f : 0.0f, q1 ? 1.0f : 0.0f);
            rf = ffma2(rf, RD2, sn);
            sref[n] = rf.x; sref[n+1] = rf.y;
            float2 f = make_float2(sft[n], sft[n+1]);
            f = ffma2(f, FD2, sn);
            sft[n] = f.x; sft[n+1] = f.y;
            sfts[n]   += f.x;
            sfts[n+1] += f.y;
            any = any || q0 || q1;
            msk |= (q0 ? 1u : 0u) << (2 * p);
            msk |= (q1 ? 1u : 0u) << (2 * p + 1);
        }
        smask[tid] = msk;
        prev = bar_red_or(any);
    }

    const float invL = 1.0f / (float)LSTEPS;
    float* o0 = out + (size_t)b * (2 * NHID) + tid * NPTF;
    float* o1 = o0 + NHID;
    #pragma unroll
    for (int i = 0; i < 2; ++i) {
        const int n = tid * NPTF + 4 * i;
        ((float4*)o0)[i] = make_float4(sfts[n]*invL, sfts[n+1]*invL,
                                       sfts[n+2]*invL, sfts[n+3]*invL);
        ((float4*)o1)[i] = make_float4(sft[n], sft[n+1], sft[n+2], sft[n+3]);
    }
}

extern "C" void kernel_launch(void* const* d_in, const int* in_sizes, int n_in,
                              void* d_out, int out_size)
{
    const float* x    = (const float*)d_in[0];
    const float* x2h  = (const float*)d_in[1];
    const float* h2h  = (const float*)d_in[2];
    const float* bias = (const float*)d_in[3];
    const float* gam  = (const float*)d_in[4];
    const float* eps  = (const float*)d_in[5];
    const float* sg   = (const float*)d_in[6];

    const int B = in_sizes[0] / LSTEPS;   // N_INP == 1
    coesn_cold<<<B, TPBC>>>(x, x2h, bias, gam, eps, sg, (float*)d_out);
    coesn_fix <<<B, TPBF>>>(x, x2h, h2h, bias, gam, eps, sg, (float*)d_out);
}

// round 9
// speedup vs baseline: 1.0831x; 1.0499x over previous
#include <cuda_runtime.h>
#include <cstdint>
#include <math.h>

#define NHID   1024
#define LSTEPS 1024
#define TPBC   256          // cold kernel: 8 warps per CTA, one CTA per row
#define NPTC   4            // cold: neurons per thread
#define NPRC   2            // cold: f32x2 pairs per thread
#define TPBF   128          // fix kernel
#define NPTF   8
#define NPRF   4
#define BMAX   4096

typedef unsigned long long u64;

__device__ int g_spiked[BMAX];   // per-row "any RF spike ever" flag

// ---- packed f32x2 ops (sm_100+) ----
__device__ __forceinline__ float2 ffma2(float2 a, float2 b, float2 c) {
    float2 d;
    asm("fma.rn.f32x2 %0, %1, %2, %3;"
        : "=l"(*(u64*)&d) : "l"(*(u64*)&a), "l"(*(u64*)&b), "l"(*(u64*)&c));
    return d;
}
__device__ __forceinline__ float2 fadd2(float2 a, float2 b) {
    float2 d;
    asm("add.rn.f32x2 %0, %1, %2;"
        : "=l"(*(u64*)&d) : "l"(*(u64*)&a), "l"(*(u64*)&b));
    return d;
}
__device__ __forceinline__ float2 fmul2(float2 a, float2 b) {
    float2 d;
    asm("mul.rn.f32x2 %0, %1, %2;"
        : "=l"(*(u64*)&d) : "l"(*(u64*)&a), "l"(*(u64*)&b));
    return d;
}

// Barrier + OR-reduction across the CTA in one BAR.RED instruction.
__device__ __forceinline__ bool bar_red_or(bool p) {
    unsigned r;
    asm volatile(
        "{\n\t"
        ".reg .pred pi, po;\n\t"
        "setp.ne.u32 pi, %1, 0;\n\t"
        "bar.red.or.pred po, 0, pi;\n\t"
        "selp.u32 %0, 1, 0, po;\n\t"
        "}"
        : "=r"(r) : "r"((unsigned)p) : "memory");
    return r != 0;
}

// ======================= COLD KERNEL (barrier-free mainloop) ==============
// While no RF spike has EVER occurred in a row, ref/ft/fts are exactly 0 and
// there is no recurrent coupling; alpha=beta=0 means an RF spike would not
// alter hy/hz. The uncoupled lif/hy/hzs trajectory is valid up to and
// including the first crossing; "did any neuron ever cross hy>1" (ref==0 =>
// spike cond (hy-1-ref)>0 <=> hy>1, Sterbenz-exact) decides everything.
// hzs = dt*hz:  hzs' = hzs*(1-dt*eps) + (-dt^2*gamma)*hy + k;  hy += hzs'.
// k = (lif>1) ? dt^2*sg : 0   (FSEL output feeds the ffma2 addend directly)
// reset: lif += k * (-1/(dt^2*sg))  == -1*spike up to 1 ulp.
// Per pair-step: fma 6 (I, lif, reset, inner, outer, hy-add)
//                alu 6 (FSETP x2, FSEL x2, FMNMX x2)   -- pipe-balanced.
__global__ __launch_bounds__(TPBC, 6)
void coesn_cold(const float* __restrict__ x,      // (B, L)
                const float* __restrict__ x2h,    // (NHID)
                const float* __restrict__ bias,   // (NHID)
                const float* __restrict__ gamma_, // (NHID)
                const float* __restrict__ eps_,   // (NHID)
                const float* __restrict__ sgain,  // scalar
                float* __restrict__ out)          // (B, 2*NHID)
{
    __shared__ float xs2[2 * LSTEPS];   // duplicated: xs2[2t]=xs2[2t+1]=x[t]

    const int tid = threadIdx.x;
    const int b   = blockIdx.x;

    // Stage duplicated input: each thread expands one float4 (4 steps).
    {
        const float4 v = ((const float4*)(x + (size_t)b * LSTEPS))[tid];
        float4* dst = ((float4*)xs2) + 2 * tid;
        dst[0] = make_float4(v.x, v.x, v.y, v.y);
        dst[1] = make_float4(v.z, v.z, v.w, v.w);
    }

    const float dt = 0.01f;
    const float A  = 1.0f - dt / 20.0f;             // LIF decay
    const float kC = dt * dt * (*sgain);            // hzs kick per LIF spike
    const float2 A2  = make_float2(A, A);
    const float2 CR2 = make_float2(-1.0f / kC, -1.0f / kC);  // reset scale

    float2 W2[NPRC], B2[NPRC], EZ2[NPRC], GN2[NPRC];
    {
        float4 a;
        a = ((const float4*)x2h)[tid];
        W2[0] = make_float2(dt*a.x, dt*a.y);  W2[1] = make_float2(dt*a.z, dt*a.w);
        a = ((const float4*)bias)[tid];
        B2[0] = make_float2(dt*a.x, dt*a.y);  B2[1] = make_float2(dt*a.z, dt*a.w);
        a = ((const float4*)eps_)[tid];
        EZ2[0] = make_float2(1.f-dt*a.x, 1.f-dt*a.y);
        EZ2[1] = make_float2(1.f-dt*a.z, 1.f-dt*a.w);
        a = ((const float4*)gamma_)[tid];
        GN2[0] = make_float2(-dt*dt*a.x, -dt*dt*a.y);
        GN2[1] = make_float2(-dt*dt*a.z, -dt*dt*a.w);
    }

    float2 lif2[NPRC], hy2[NPRC], hzs2[NPRC];
    #pragma unroll
    for (int p = 0; p < NPRC; ++p) {
        lif2[p] = make_float2(0.f, 0.f);
        hy2[p]  = make_float2(0.f, 0.f);
        hzs2[p] = make_float2(0.f, 0.f);
    }
    float2 mx2 = make_float2(-1.f, -1.f);   // running max of hy (both lanes)

    __syncthreads();   // xs2 ready

    const float4* xv = (const float4*)xs2;
    #pragma unroll 1
    for (int it = 0; it < LSTEPS / 8; ++it) {
        float4 q[4];
        #pragma unroll
        for (int i = 0; i < 4; ++i) q[i] = xv[it * 4 + i];   // 8 steps of pairs
        #pragma unroll
        for (int s = 0; s < 8; ++s) {
            const float* qf = (const float*)q;
            const float2 XT2 = make_float2(qf[2 * s], qf[2 * s + 1]);
            #pragma unroll
            for (int p = 0; p < NPRC; ++p) {
                float2 I = ffma2(XT2, W2[p], B2[p]);       // dt*(xt*w + b)
                lif2[p] = ffma2(lif2[p], A2, I);           // v = v*A + dt*I
                float2 k;
                k.x = (lif2[p].x > 1.0f) ? kC : 0.0f;      // FSETP+FSEL
                k.y = (lif2[p].y > 1.0f) ? kC : 0.0f;      // FSETP+FSEL
                lif2[p] = ffma2(k, CR2, lif2[p]);          // soft reset (-1*s)
                hzs2[p] = ffma2(hzs2[p], EZ2[p], ffma2(GN2[p], hy2[p], k));
                hy2[p]  = fadd2(hy2[p], hzs2[p]);          // hy += dt*hz
                mx2.x = fmaxf(mx2.x, hy2[p].x);            // FMNMX
                mx2.y = fmaxf(mx2.y, hy2[p].y);            // FMNMX
            }
        }
    }

    const bool ever = bar_red_or(fmaxf(mx2.x, mx2.y) > 1.0f);
    if (tid == 0) g_spiked[b] = ever ? 1 : 0;

    // Zero output (correct if no spike; fix kernel overwrites otherwise).
    float* o0 = out + (size_t)b * (2 * NHID) + tid * NPTC;
    const float4 z = make_float4(0.f, 0.f, 0.f, 0.f);
    ((float4*)o0)[0] = z;
    ((float4*)(o0 + NHID))[0] = z;
}

// ======================= FIX KERNEL (general coupled path) ================
// Full dynamics with recurrent h2h gather + ref/ft/fts, only for flagged rows
// (expected: none on this data; correctness safety net for any input).
__global__ __launch_bounds__(TPBF)
void coesn_fix(const float* __restrict__ x,
               const float* __restrict__ x2h,
               const float* __restrict__ h2h,
               const float* __restrict__ bias,
               const float* __restrict__ gamma_,
               const float* __restrict__ eps_,
               const float* __restrict__ sgain,
               float* __restrict__ out)
{
    const int b = blockIdx.x;
    if (g_spiked[b] == 0) return;      // uniform per CTA

    __shared__ float    xs[LSTEPS];
    __shared__ unsigned smask[TPBF];
    __shared__ float    sref[NHID], sft[NHID], sfts[NHID];

    const int tid = threadIdx.x;

    {
        const float4* xr = (const float4*)(x + (size_t)b * LSTEPS);
        ((float4*)xs)[tid]        = xr[tid];
        ((float4*)xs)[tid + TPBF] = xr[tid + TPBF];
    }

    const float dt = 0.01f;
    const float A  = 1.0f - dt / 20.0f;
    const float sg = *sgain;
    const float RD = expf(-dt / 0.25f);
    const float FD = expf(-dt / 10.0f);

    const float2 A2     = make_float2(A, A);
    const float2 DT2    = make_float2(dt, dt);
    const float2 NDTSG2 = make_float2(-dt * sg, -dt * sg);
    const float2 RD2    = make_float2(RD, RD);
    const float2 FD2    = make_float2(FD, FD);

    float2 W2[NPRF], B2[NPRF], EZ2[NPRF], GN2[NPRF];
    #pragma unroll
    for (int i = 0; i < 2; ++i) {
        float4 a;
        a = ((const float4*)x2h)[tid * 2 + i];
        W2[2*i]   = make_float2(dt*a.x, dt*a.y);
        W2[2*i+1] = make_float2(dt*a.z, dt*a.w);
        a = ((const float4*)bias)[tid * 2 + i];
        B2[2*i]   = make_float2(dt*a.x, dt*a.y);
        B2[2*i+1] = make_float2(dt*a.z, dt*a.w);
        a = ((const float4*)eps_)[tid * 2 + i];
        EZ2[2*i]   = make_float2(1.f-dt*a.x, 1.f-dt*a.y);
        EZ2[2*i+1] = make_float2(1.f-dt*a.z, 1.f-dt*a.w);
        a = ((const float4*)gamma_)[tid * 2 + i];
        GN2[2*i]   = make_float2(-dt*a.x, -dt*a.y);
        GN2[2*i+1] = make_float2(-dt*a.z, -dt*a.w);
    }

    float2 lif2[NPRF], hy2[NPRF], hz2[NPRF];
    #pragma unroll
    for (int p = 0; p < NPRF; ++p) {
        lif2[p] = make_float2(0.f, 0.f);
        hy2[p]  = make_float2(0.f, 0.f);
        hz2[p]  = make_float2(0.f, 0.f);
    }
    #pragma unroll
    for (int q = 0; q < NPTF; ++q) {
        const int n = tid * NPTF + q;
        sref[n] = 0.f; sft[n] = 0.f; sfts[n] = 0.f;
    }
    smask[tid] = 0u;
    __syncthreads();

    bool prev = false;
    #pragma unroll 1
    for (int t = 0; t < LSTEPS; ++t) {
        const float  xt  = xs[t];
        const float2 XT2 = make_float2(xt, xt);

        float2 acc[NPRF];
        #pragma unroll
        for (int p = 0; p < NPRF; ++p) acc[p] = make_float2(0.f, 0.f);

        if (prev) {
            for (int w = 0; w < TPBF; ++w) {
                unsigned mm_ = smask[w];
                while (mm_) {
                    const int k = __ffs(mm_) - 1; mm_ &= mm_ - 1;
                    const int j = w * NPTF + k;
                    const float4* hp =
                        (const float4*)(h2h + (size_t)j * NHID + tid * NPTF);
                    #pragma unroll
                    for (int i = 0; i < 2; ++i) {
                        float4 h = __ldg(hp + i);
                        acc[2*i].x   += h.x; acc[2*i].y   += h.y;
                        acc[2*i+1].x += h.z; acc[2*i+1].y += h.w;
                    }
                }
            }
        }

        bool any = false;
        unsigned msk = 0;
        #pragma unroll
        for (int p = 0; p < NPRF; ++p) {
            float2 I = ffma2(XT2, W2[p], B2[p]);
            I = ffma2(DT2, acc[p], I);
            lif2[p] = ffma2(lif2[p], A2, I);
            const bool l0 = lif2[p].x > 1.0f;
            const bool l1 = lif2[p].y > 1.0f;
            float2 ms = make_float2(l0 ? -1.0f : 0.0f, l1 ? -1.0f : 0.0f);
            lif2[p] = fadd2(lif2[p], ms);
            float2 k = fmul2(ms, NDTSG2);
            hz2[p] = ffma2(hz2[p], EZ2[p], ffma2(GN2[p], hy2[p], k));
            hy2[p] = ffma2(DT2, hz2[p], hy2[p]);

            const int n = tid * NPTF + 2 * p;
            float2 rf = make_float2(sref[n], sref[n+1]);
            const bool q0 = (hy2[p].x - 1.0f) > rf.x;
            const bool q1 = (hy2[p].y - 1.0f) > rf.y;
            float2 sn = make_float2(q0 ? 1.0f : 0.0f, q1 ? 1.0f : 0.0f);
            rf = ffma2(rf, RD2, sn);
            sref[n] = rf.x; sref[n+1] = rf.y;
            float2 f = make_float2(sft[n], sft[n+1]);
            f = ffma2(f, FD2, sn);
            sft[n] = f.x; sft[n+1] = f.y;
            sfts[n]   += f.x;
            sfts[n+1] += f.y;
            any = any || q0 || q1;
            msk |= (q0 ? 1u : 0u) << (2 * p);
            msk |= (q1 ? 1u : 0u) << (2 * p + 1);
        }
        smask[tid] = msk;
        prev = bar_red_or(any);
    }

    const float invL = 1.0f / (float)LSTEPS;
    float* o0 = out + (size_t)b * (2 * NHID) + tid * NPTF;
    float* o1 = o0 + NHID;
    #pragma unroll
    for (int i = 0; i < 2; ++i) {
        const int n = tid * NPTF + 4 * i;
        ((float4*)o0)[i] = make_float4(sfts[n]*invL, sfts[n+1]*invL,
                                       sfts[n+2]*invL, sfts[n+3]*invL);
        ((float4*)o1)[i] = make_float4(sft[n], sft[n+1], sft[n+2], sft[n+3]);
    }
}

extern "C" void kernel_launch(void* const* d_in, const int* in_sizes, int n_in,
                              void* d_out, int out_size)
{
    const float* x    = (const float*)d_in[0];
    const float* x2h  = (const float*)d_in[1];
    const float* h2h  = (const float*)d_in[2];
    const float* bias = (const float*)d_in[3];
    const float* gam  = (const float*)d_in[4];
    const float* eps  = (const float*)d_in[5];
    const float* sg   = (const float*)d_in[6];

    const int B = in_sizes[0] / LSTEPS;   // N_INP == 1
    coesn_cold<<<B, TPBC>>>(x, x2h, bias, gam, eps, sg, (float*)d_out);
    coesn_fix <<<B, TPBF>>>(x, x2h, h2h, bias, gam, eps, sg, (float*)d_out);
}